// round 3
// baseline (speedup 1.0000x reference)
#include <cuda_runtime.h>

// ---------------------------------------------------------------------------
// YoloLoss: full reduction over [N=32768, H=6, W=8, C=14] fp32 tensors.
// SINGLE kernel: block stages its 512 cells (2 x 28KB) through shared memory
// with coalesced float4 streaming loads, computes per-cell loss, block-reduces,
// atomicAdd's a double scratch scalar, and the last finishing block finalizes
// the output and resets the scratch state (so graph replays are deterministic).
// ---------------------------------------------------------------------------

#define CELL_F 14
#define TPB 512
#define FLOATS_PER_BLOCK (TPB * CELL_F)        // 7168 floats per tensor per block
#define VEC4_PER_BLOCK (FLOATS_PER_BLOCK / 4)  // 1792

#define LAMBDA_COORD 8.0f
#define LAMBDA_CLASS 0.7f
#define EPS_IOU 1e-10f

__device__ double g_yolo_acc;          // zero-initialized; reset by last block
__device__ unsigned int g_yolo_count;  // zero-initialized; reset by last block

__device__ __forceinline__ float warp_reduce_sum(float v) {
    #pragma unroll
    for (int off = 16; off > 0; off >>= 1)
        v += __shfl_down_sync(0xFFFFFFFFu, v, off);
    return v;
}

__global__ void __launch_bounds__(TPB)
yolo_fused_kernel(const float* __restrict__ pred,
                  const float* __restrict__ gt,
                  long long total_elems,
                  long long n_batch,
                  float* __restrict__ out)
{
    __shared__ float so[FLOATS_PER_BLOCK];
    __shared__ float sg[FLOATS_PER_BLOCK];

    const long long base = (long long)blockIdx.x * FLOATS_PER_BLOCK;

    // ---- coalesced float4 staging (streaming: evict-first) ----
    {
        const float4* p4 = reinterpret_cast<const float4*>(pred + base);
        const float4* g4 = reinterpret_cast<const float4*>(gt + base);
        const long long rem4 = (total_elems - base) >> 2;  // float4s left
        float4* so4 = reinterpret_cast<float4*>(so);
        float4* sg4 = reinterpret_cast<float4*>(sg);
        #pragma unroll 4
        for (int i = threadIdx.x; i < VEC4_PER_BLOCK; i += TPB) {
            if ((long long)i < rem4) {
                so4[i] = __ldcs(&p4[i]);
                sg4[i] = __ldcs(&g4[i]);
            }
        }
    }
    __syncthreads();

    // ---- per-cell loss ----
    float contrib = 0.0f;
    const long long cells = total_elems / CELL_F;
    const long long cell = (long long)blockIdx.x * TPB + threadIdx.x;

    if (cell < cells) {
        const float* o = &so[threadIdx.x * CELL_F];
        const float* g = &sg[threadIdx.x * CELL_F];

        const float obj_flag = g[4];  // exactly 0.0f or 1.0f
        if (obj_flag > 0.0f) {
            // gt reference box (box 0 of gt)
            const float gx = g[0], gy = g[1];
            const float gw = g[2] * g[2], gh = g[3] * g[3];
            const float garea = gw * gh;

            float iou[2];
            #pragma unroll
            for (int b = 0; b < 2; b++) {
                const float x = o[5 * b + 0];
                const float y = o[5 * b + 1];
                const float w = o[5 * b + 2] * o[5 * b + 2];
                const float h = o[5 * b + 3] * o[5 * b + 3];
                const float left  = fmaxf(x - 0.5f * w, gx - 0.5f * gw);
                const float right = fminf(x + 0.5f * w, gx + 0.5f * gw);
                const float top   = fmaxf(y - 0.5f * h, gy - 0.5f * gh);
                const float bot   = fminf(y + 0.5f * h, gy + 0.5f * gh);
                const float inter = fmaxf(right - left, 0.0f) * fmaxf(bot - top, 0.0f);
                const float uni   = w * h + garea - inter;
                iou[b] = inter / (uni + EPS_IOU);
            }
            // jnp.argmax picks FIRST max -> responsible=1 only on strict >
            const int idx = (iou[1] > iou[0]) ? 1 : 0;
            const float max_iou = fmaxf(iou[0], iou[1]);

            const float* pr = o + 5 * idx;       // responsible pred box
            const float* po = o + 5 * (1 - idx); // other pred box
            const float* gr = g + 5 * idx;
            const float* go = g + 5 * (1 - idx);

            float loc = 0.0f;
            #pragma unroll
            for (int c = 0; c < 4; c++) {
                const float d = pr[c] - gr[c];
                loc = fmaf(d, d, loc);
            }
            const float dc = pr[4] - max_iou;
            const float conf = dc * dc;
            const float dn = po[4] - go[4];
            const float nobox = dn * dn;

            float cls = 0.0f;
            #pragma unroll
            for (int c = 10; c < 14; c++) {
                const float d = o[c] - g[c];
                cls = fmaf(d, d, cls);
            }
            contrib = conf + LAMBDA_COORD * loc + nobox + LAMBDA_CLASS * cls;
        } else {
            const float d4 = o[4] - g[4];
            const float d9 = o[9] - g[9];
            contrib = d4 * d4 + d9 * d9;  // LAMBDA_NOOBJ = 1
        }
    }

    // ---- block reduction ----
    __shared__ float warp_sums[TPB / 32];
    float v = warp_reduce_sum(contrib);
    const int wid = threadIdx.x >> 5;
    const int lid = threadIdx.x & 31;
    if (lid == 0) warp_sums[wid] = v;
    __syncthreads();

    if (threadIdx.x == 0) {
        float s = 0.0f;
        #pragma unroll
        for (int i = 0; i < TPB / 32; i++) s += warp_sums[i];

        atomicAdd(&g_yolo_acc, (double)s);
        __threadfence();
        const unsigned int ticket = atomicAdd(&g_yolo_count, 1u);
        if (ticket == gridDim.x - 1) {
            // last block: all other blocks' atomics are visible (L2-coherent,
            // ordered before their counter increment by the threadfence).
            const double total = *((volatile double*)&g_yolo_acc);
            out[0] = (float)(total / (double)n_batch);
            // reset scratch state for the next graph replay
            *((volatile double*)&g_yolo_acc) = 0.0;
            *((volatile unsigned int*)&g_yolo_count) = 0u;
        }
    }
}

extern "C" void kernel_launch(void* const* d_in, const int* in_sizes, int n_in,
                              void* d_out, int out_size)
{
    const float* pred = (const float*)d_in[0];   // 'output'
    const float* gt   = (const float*)d_in[1];   // 'ground_truth'
    float* out = (float*)d_out;

    const long long total_elems = (long long)in_sizes[0];       // N*H*W*C
    const long long cells = total_elems / CELL_F;               // N*H*W
    const long long n_batch = total_elems / (6LL * 8 * CELL_F); // N
    const int grid = (int)((cells + TPB - 1) / TPB);            // 3072

    yolo_fused_kernel<<<grid, TPB>>>(pred, gt, total_elems, n_batch, out);
}

// round 5
// speedup vs baseline: 1.3053x; 1.3053x over previous
#include <cuda_runtime.h>
#include <cstdint>

// ---------------------------------------------------------------------------
// YoloLoss on [N=32768, 6, 8, 14] fp32: persistent double-buffered
// cp.async.bulk (TMA bulk) pipeline. 444 persistent CTAs x 256 threads.
// Tile = 256 cells (14336 B per tensor). Producer thread issues bulk copies
// into stage s with mbarrier expect_tx; block parity-waits, computes one cell
// per thread, __syncthreads, then issues tile j+2 into the freed stage.
// Last-finishing block finalizes out[0] and resets scratch state.
// ---------------------------------------------------------------------------

#define CELL_F 14
#define TPB 256
#define TILE_CELLS 256
#define TILE_FLOATS (TILE_CELLS * CELL_F)   // 3584 floats
#define TILE_BYTES  (TILE_FLOATS * 4)       // 14336 bytes
#define STAGES 2
#define GRID_BLOCKS 444                     // 148 SMs x 3 (smem-limited)

#define LAMBDA_COORD 8.0f
#define LAMBDA_CLASS 0.7f
#define EPS_IOU 1e-10f

__device__ double g_yolo_acc;          // zero-init; reset by last block
__device__ unsigned int g_yolo_count;  // zero-init; reset by last block

__device__ __forceinline__ uint32_t smem_u32(const void* p) {
    return (uint32_t)__cvta_generic_to_shared((void*)p);
}

__device__ __forceinline__ void mbar_init(uint32_t mb, uint32_t count) {
    asm volatile("mbarrier.init.shared::cta.b64 [%0], %1;"
                 :: "r"(mb), "r"(count) : "memory");
}

__device__ __forceinline__ void mbar_wait(uint32_t mb, uint32_t phase) {
    uint32_t done = 0;
    while (!done) {
        asm volatile(
            "{\n\t.reg .pred p;\n\t"
            "mbarrier.try_wait.parity.acquire.cta.shared::cta.b64 p, [%1], %2, 0x989680;\n\t"
            "selp.b32 %0, 1, 0, p;\n\t}"
            : "=r"(done) : "r"(mb), "r"(phase) : "memory");
    }
}

__device__ __forceinline__ void issue_tile(const float* __restrict__ pred,
                                           const float* __restrict__ gt,
                                           float* dynsmem, int s,
                                           long long tile, uint32_t mb)
{
    asm volatile("mbarrier.arrive.expect_tx.shared::cta.b64 _, [%0], %1;"
                 :: "r"(mb), "r"(2u * TILE_BYTES) : "memory");
    const char* srcp = (const char*)pred + tile * (long long)TILE_BYTES;
    const char* srcg = (const char*)gt   + tile * (long long)TILE_BYTES;
    uint32_t dso = smem_u32(dynsmem + (size_t)s * 2 * TILE_FLOATS);
    uint32_t dsg = dso + TILE_BYTES;
    asm volatile("cp.async.bulk.shared::cluster.global.mbarrier::complete_tx::bytes "
                 "[%0], [%1], %2, [%3];"
                 :: "r"(dso), "l"(srcp), "r"((uint32_t)TILE_BYTES), "r"(mb) : "memory");
    asm volatile("cp.async.bulk.shared::cluster.global.mbarrier::complete_tx::bytes "
                 "[%0], [%1], %2, [%3];"
                 :: "r"(dsg), "l"(srcg), "r"((uint32_t)TILE_BYTES), "r"(mb) : "memory");
}

__device__ __forceinline__ float cell_loss(const float* __restrict__ o,
                                           const float* __restrict__ g)
{
    const float obj_flag = g[4];  // exactly 0.0f or 1.0f
    if (obj_flag > 0.0f) {
        const float gx = g[0], gy = g[1];
        const float gw = g[2] * g[2], gh = g[3] * g[3];
        const float garea = gw * gh;

        float iou[2];
        #pragma unroll
        for (int b = 0; b < 2; b++) {
            const float x = o[5 * b + 0];
            const float y = o[5 * b + 1];
            const float w = o[5 * b + 2] * o[5 * b + 2];
            const float h = o[5 * b + 3] * o[5 * b + 3];
            const float left  = fmaxf(x - 0.5f * w, gx - 0.5f * gw);
            const float right = fminf(x + 0.5f * w, gx + 0.5f * gw);
            const float top   = fmaxf(y - 0.5f * h, gy - 0.5f * gh);
            const float bot   = fminf(y + 0.5f * h, gy + 0.5f * gh);
            const float inter = fmaxf(right - left, 0.0f) * fmaxf(bot - top, 0.0f);
            const float uni   = w * h + garea - inter;
            iou[b] = inter / (uni + EPS_IOU);
        }
        // jnp.argmax picks FIRST max -> responsible=1 only on strict >
        const int idx = (iou[1] > iou[0]) ? 1 : 0;
        const float max_iou = fmaxf(iou[0], iou[1]);

        const float* pr = o + 5 * idx;
        const float* po = o + 5 * (1 - idx);
        const float* gr = g + 5 * idx;
        const float* go = g + 5 * (1 - idx);

        float loc = 0.0f;
        #pragma unroll
        for (int c = 0; c < 4; c++) {
            const float d = pr[c] - gr[c];
            loc = fmaf(d, d, loc);
        }
        const float dc = pr[4] - max_iou;
        const float dn = po[4] - go[4];

        float cls = 0.0f;
        #pragma unroll
        for (int c = 10; c < 14; c++) {
            const float d = o[c] - g[c];
            cls = fmaf(d, d, cls);
        }
        return dc * dc + LAMBDA_COORD * loc + dn * dn + LAMBDA_CLASS * cls;
    } else {
        const float d4 = o[4] - g[4];
        const float d9 = o[9] - g[9];
        return d4 * d4 + d9 * d9;  // LAMBDA_NOOBJ = 1
    }
}

__device__ __forceinline__ float warp_reduce_sum(float v) {
    #pragma unroll
    for (int off = 16; off > 0; off >>= 1)
        v += __shfl_down_sync(0xFFFFFFFFu, v, off);
    return v;
}

extern __shared__ float dynsmem[];  // [STAGES][2][TILE_FLOATS]

__global__ void __launch_bounds__(TPB)
yolo_pipe_kernel(const float* __restrict__ pred,
                 const float* __restrict__ gt,
                 long long cells,
                 long long n_batch,
                 float* __restrict__ out)
{
    __shared__ __align__(8) unsigned long long mbar_full[STAGES];
    __shared__ float warp_sums[TPB / 32];

    const int tid = threadIdx.x;
    const long long tiles = cells / TILE_CELLS;

    if (tid == 0) {
        #pragma unroll
        for (int s = 0; s < STAGES; s++)
            mbar_init(smem_u32(&mbar_full[s]), 1);
    }
    __syncthreads();

    // number of tiles this block will process
    long long nt = 0;
    if ((long long)blockIdx.x < tiles)
        nt = (tiles - blockIdx.x + gridDim.x - 1) / gridDim.x;

    // prologue: fill both stages
    if (tid == 0) {
        if (nt > 0) issue_tile(pred, gt, dynsmem, 0, blockIdx.x, smem_u32(&mbar_full[0]));
        if (nt > 1) issue_tile(pred, gt, dynsmem, 1, blockIdx.x + (long long)gridDim.x,
                               smem_u32(&mbar_full[1]));
    }

    uint32_t ph0 = 0, ph1 = 0;
    float acc = 0.0f;

    for (long long j = 0; j < nt; j++) {
        const int s = (int)(j & 1);
        if (s == 0) { mbar_wait(smem_u32(&mbar_full[0]), ph0); ph0 ^= 1; }
        else        { mbar_wait(smem_u32(&mbar_full[1]), ph1); ph1 ^= 1; }

        const float* o = dynsmem + (size_t)s * 2 * TILE_FLOATS + tid * CELL_F;
        const float* g = o + TILE_FLOATS;
        acc += cell_loss(o, g);

        __syncthreads();  // all threads done reading stage s

        if (tid == 0 && j + 2 < nt) {
            const long long tile = blockIdx.x + (j + 2) * (long long)gridDim.x;
            issue_tile(pred, gt, dynsmem, s, tile, smem_u32(&mbar_full[s]));
        }
    }

    // remainder cells (cells % TILE_CELLS), handled by block 0 via direct loads
    if (blockIdx.x == 0) {
        const long long rem_start = tiles * TILE_CELLS;
        for (long long c = rem_start + tid; c < cells; c += TPB) {
            float oc[CELL_F], gc[CELL_F];
            #pragma unroll
            for (int k = 0; k < CELL_F; k++) {
                oc[k] = __ldg(pred + c * CELL_F + k);
                gc[k] = __ldg(gt   + c * CELL_F + k);
            }
            acc += cell_loss(oc, gc);
        }
    }

    // ---- block reduction ----
    float v = warp_reduce_sum(acc);
    const int wid = tid >> 5;
    const int lid = tid & 31;
    if (lid == 0) warp_sums[wid] = v;
    __syncthreads();

    if (tid == 0) {
        float s = 0.0f;
        #pragma unroll
        for (int i = 0; i < TPB / 32; i++) s += warp_sums[i];

        atomicAdd(&g_yolo_acc, (double)s);
        __threadfence();
        const unsigned int ticket = atomicAdd(&g_yolo_count, 1u);
        if (ticket == gridDim.x - 1) {
            const double total = *((volatile double*)&g_yolo_acc);
            out[0] = (float)(total / (double)n_batch);
            *((volatile double*)&g_yolo_acc) = 0.0;
            *((volatile unsigned int*)&g_yolo_count) = 0u;
        }
    }
}

extern "C" void kernel_launch(void* const* d_in, const int* in_sizes, int n_in,
                              void* d_out, int out_size)
{
    const float* pred = (const float*)d_in[0];   // 'output'
    const float* gt   = (const float*)d_in[1];   // 'ground_truth'
    float* out = (float*)d_out;

    const long long total_elems = (long long)in_sizes[0];       // N*H*W*C
    const long long cells = total_elems / CELL_F;               // N*H*W
    const long long n_batch = total_elems / (6LL * 8 * CELL_F); // N

    const int dyn_bytes = STAGES * 2 * TILE_BYTES;              // 57344

    cudaFuncSetAttribute(yolo_pipe_kernel,
                         cudaFuncAttributeMaxDynamicSharedMemorySize, dyn_bytes);

    long long tiles = cells / TILE_CELLS;
    int grid = GRID_BLOCKS;
    if (tiles > 0 && tiles < grid) grid = (int)tiles;
    if (grid < 1) grid = 1;

    yolo_pipe_kernel<<<grid, TPB, dyn_bytes>>>(pred, gt, cells, n_batch, out);
}